// round 1
// baseline (speedup 1.0000x reference)
#include <cuda_runtime.h>
#include <math.h>

// OptNet_2525440770614
//
// Reference analysis: the fc1+ReLU path over x/W1/b1 is dead code (result
// discarded). Output = log_softmax of the KKT solution of a 10-dim QP built
// from L (10x10), p, G, z0, s0 only. Total real work ~1.5 kFLOP.
//
// Strategy: single <<<1,1>>> kernel, all state in registers/local, fp64
// internally (Cholesky solve of a 10x10 SPD system), fp32 output (1,10).

#define NC 10
#define QP_EPS 1e-4

__global__ void optnet_qp_kernel(const float* __restrict__ L,
                                 const float* __restrict__ p,
                                 const float* __restrict__ G,
                                 const float* __restrict__ z0,
                                 const float* __restrict__ s0,
                                 float* __restrict__ out) {
    // Single-thread scalar solve; trivially cheap.
    if (threadIdx.x != 0 || blockIdx.x != 0) return;

    // ---- Build Q = tril(L) tril(L)^T + eps*I ----
    double Q[NC][NC];
    #pragma unroll
    for (int i = 0; i < NC; i++) {
        #pragma unroll
        for (int j = 0; j < NC; j++) {
            int m = (i < j) ? i : j;   // tril: row r has cols 0..r
            double s = 0.0;
            for (int k = 0; k <= m; k++)
                s += (double)L[i * NC + k] * (double)L[j * NC + k];
            if (i == j) s += QP_EPS;
            Q[i][j] = s;
        }
    }

    double gv[NC];
    #pragma unroll
    for (int i = 0; i < NC; i++) gv[i] = (double)G[i];

    double h = (double)s0[0];
    #pragma unroll
    for (int i = 0; i < NC; i++) h += gv[i] * (double)z0[i];

    // ---- Cholesky: Q = C C^T (SPD by construction) ----
    double C[NC][NC];
    #pragma unroll
    for (int i = 0; i < NC; i++) {
        for (int j = 0; j <= i; j++) {
            double s = Q[i][j];
            for (int k = 0; k < j; k++) s -= C[i][k] * C[j][k];
            if (i == j) C[i][i] = sqrt(s);
            else        C[i][j] = s / C[j][j];
        }
    }

    // ---- Two solves: Q z_unc = -p  and  Q qig = g ----
    double zu[NC], qg[NC], y[NC];

    // solve for z_unc (rhs = -p)
    #pragma unroll
    for (int i = 0; i < NC; i++) {
        double s = -(double)p[i];
        for (int k = 0; k < i; k++) s -= C[i][k] * y[k];
        y[i] = s / C[i][i];
    }
    for (int i = NC - 1; i >= 0; i--) {
        double s = y[i];
        for (int k = i + 1; k < NC; k++) s -= C[k][i] * zu[k];
        zu[i] = s / C[i][i];
    }

    // solve for qig (rhs = g)
    #pragma unroll
    for (int i = 0; i < NC; i++) {
        double s = gv[i];
        for (int k = 0; k < i; k++) s -= C[i][k] * y[k];
        y[i] = s / C[i][i];
    }
    for (int i = NC - 1; i >= 0; i--) {
        double s = y[i];
        for (int k = i + 1; k < NC; k++) s -= C[k][i] * qg[k];
        qg[i] = s / C[i][i];
    }

    // ---- KKT single-constraint clamp ----
    double viol = -h, denom = 0.0;
    #pragma unroll
    for (int i = 0; i < NC; i++) {
        viol  += gv[i] * zu[i];
        denom += gv[i] * qg[i];
    }
    double lam = (viol > 0.0 ? viol : 0.0) / denom;

    double z[NC];
    #pragma unroll
    for (int i = 0; i < NC; i++) z[i] = zu[i] - lam * qg[i];

    // ---- log_softmax ----
    double mx = z[0];
    #pragma unroll
    for (int i = 1; i < NC; i++) mx = (z[i] > mx) ? z[i] : mx;
    double se = 0.0;
    #pragma unroll
    for (int i = 0; i < NC; i++) se += exp(z[i] - mx);
    double lse = log(se);
    #pragma unroll
    for (int i = 0; i < NC; i++)
        out[i] = (float)(z[i] - mx - lse);
}

extern "C" void kernel_launch(void* const* d_in, const int* in_sizes, int n_in,
                              void* d_out, int out_size) {
    // metadata order: x, W1, b1, L, p, G, z0, s0
    const float* L  = (const float*)d_in[3];
    const float* p  = (const float*)d_in[4];
    const float* G  = (const float*)d_in[5];
    const float* z0 = (const float*)d_in[6];
    const float* s0 = (const float*)d_in[7];
    float* out = (float*)d_out;
    (void)in_sizes; (void)n_in; (void)out_size;

    optnet_qp_kernel<<<1, 1>>>(L, p, G, z0, s0, out);
}

// round 2
// speedup vs baseline: 2.4681x; 2.4681x over previous
#include <cuda_runtime.h>
#include <math.h>

// OptNet_2525440770614 — warp-parallel 10-dim QP + log_softmax.
//
// R1 post-mortem: single-thread fp64 version was latency-bound (78us kernel,
// ~140k serial cycles: DFMA lat 47, fp64 div/sqrt hundreds of cycles each,
// double exp/log). This version:
//  - 32-lane warp parallelism for Q build / Cholesky / solves
//  - rsqrt-based Cholesky: 1/C[j][j] == rsqrt(diag) -> no fp64 divides at all
//  - both RHS substituted simultaneously on disjoint lane groups
//  - fp32 softmax epilogue
// Predicted kernel time ~5us.

#define NC 10
#define QP_EPS 1e-4
#define FULL 0xffffffffu

__global__ void __launch_bounds__(32, 1)
optnet_qp_warp(const float* __restrict__ L,
               const float* __restrict__ p,
               const float* __restrict__ G,
               const float* __restrict__ z0,
               const float* __restrict__ s0,
               float* __restrict__ out) {
    __shared__ double sQ[NC][NC];     // Q, overwritten in place by Cholesky C (lower)
    __shared__ double rdiag[NC];      // 1 / C[j][j] (== rsqrt of updated diag)
    __shared__ double sg[NC];         // G row
    __shared__ double s_zu[NC], s_qg[NC];

    const int lane = threadIdx.x;

    // ---- load g ----
    if (lane < NC) sg[lane] = (double)G[lane];

    // ---- build Q = tril(L) tril(L)^T + eps I, 100 entries over 32 lanes ----
    #pragma unroll
    for (int t = 0; t < 4; t++) {
        int idx = lane + 32 * t;
        if (idx < NC * NC) {
            int i = idx / NC, j = idx % NC;
            int m = (i < j) ? i : j;
            double s = 0.0;
            for (int k = 0; k <= m; k++)
                s += (double)L[i * NC + k] * (double)L[j * NC + k];
            if (i == j) s += QP_EPS;
            sQ[i][j] = s;
        }
    }
    __syncwarp();

    // ---- h = s0 + g . z0 (shuffle reduce) ----
    double hacc = (lane < NC) ? sg[lane] * (double)z0[lane] : 0.0;
    #pragma unroll
    for (int o = 16; o >= 1; o >>= 1) hacc += __shfl_xor_sync(FULL, hacc, o);
    const double h = hacc + (double)s0[0];

    // ---- per-lane trailing-update pair assignments: 55 lower-tri pairs ----
    int pi[2], pk[2];
    #pragma unroll
    for (int t = 0; t < 2; t++) {
        int idx = lane + 32 * t;
        pi[t] = -1; pk[t] = -1;
        if (idx < 55) {
            int i = 0;
            while ((i + 1) * (i + 2) / 2 <= idx) i++;
            pi[t] = i;
            pk[t] = idx - i * (i + 1) / 2;
        }
    }

    // ---- warp Cholesky, right-looking, rsqrt-based ----
    for (int j = 0; j < NC; j++) {
        // 1/sqrt of updated diagonal -> also equals 1/C[j][j]
        if (lane == j) rdiag[j] = rsqrt(sQ[j][j]);
        __syncwarp();
        double rs = rdiag[j];
        // scale column j:  C[i][j] = s_i * rs  (diag: C[j][j] = s*rs = sqrt(s))
        if (lane >= j && lane < NC) sQ[lane][j] *= rs;
        __syncwarp();
        // trailing update Q[i][k] -= C[i][j]*C[k][j] for j < k <= i
        #pragma unroll
        for (int t = 0; t < 2; t++) {
            if (pk[t] > j) sQ[pi[t]][pk[t]] -= sQ[pi[t]][j] * sQ[pk[t]][j];
        }
        __syncwarp();
    }

    // ---- two simultaneous solves: lanes 0-9 rhs=-p, lanes 16-25 rhs=g ----
    const int base = (lane < 16) ? 0 : 16;
    const int row0 = lane - base;
    const int row  = (row0 < NC) ? row0 : NC - 1;   // clamped for safe reads
    const bool act = (row0 < NC);

    double acc;
    if (base == 0) acc = act ? -(double)p[row] : 0.0;
    else           acc = act ? sg[row] : 0.0;

    // forward: C y = b
    double yreg = 0.0;
    #pragma unroll
    for (int j = 0; j < NC; j++) {
        double v = acc * rdiag[j];
        double yj = __shfl_sync(FULL, v, base + j);
        if (act && row0 == j) yreg = yj;
        if (act && row0 > j)  acc -= sQ[row][j] * yj;
    }
    // backward: C^T x = y
    acc = yreg;
    double xreg = 0.0;
    #pragma unroll
    for (int j = NC - 1; j >= 0; j--) {
        double v = acc * rdiag[j];
        double xj = __shfl_sync(FULL, v, base + j);
        if (act && row0 == j) xreg = xj;
        if (act && row0 < j)  acc -= sQ[j][row] * xj;
    }

    if (act && base == 0)  s_zu[row0] = xreg;
    if (act && base == 16) s_qg[row0] = xreg;
    __syncwarp();

    // ---- viol = g.zu - h ; denom = g.qg ----
    double a = (lane < NC) ? sg[lane] * s_zu[lane] : 0.0;
    #pragma unroll
    for (int o = 16; o >= 1; o >>= 1) a += __shfl_xor_sync(FULL, a, o);
    double viol = a - h;

    double b = (lane < NC) ? sg[lane] * s_qg[lane] : 0.0;
    #pragma unroll
    for (int o = 16; o >= 1; o >>= 1) b += __shfl_xor_sync(FULL, b, o);
    double lam = ((viol > 0.0) ? viol : 0.0) / b;

    // ---- z, fp32 log_softmax ----
    float zf = (lane < NC) ? (float)(s_zu[lane] - lam * s_qg[lane]) : -INFINITY;

    float mx = zf;
    #pragma unroll
    for (int o = 16; o >= 1; o >>= 1) {
        float o2 = __shfl_xor_sync(FULL, mx, o);
        mx = fmaxf(mx, o2);
    }
    float e = (lane < NC) ? expf(zf - mx) : 0.0f;
    float se = e;
    #pragma unroll
    for (int o = 16; o >= 1; o >>= 1) se += __shfl_xor_sync(FULL, se, o);
    float lse = logf(se);

    if (lane < NC) out[lane] = zf - mx - lse;
}

extern "C" void kernel_launch(void* const* d_in, const int* in_sizes, int n_in,
                              void* d_out, int out_size) {
    // metadata order: x, W1, b1, L, p, G, z0, s0
    const float* L  = (const float*)d_in[3];
    const float* p  = (const float*)d_in[4];
    const float* G  = (const float*)d_in[5];
    const float* z0 = (const float*)d_in[6];
    const float* s0 = (const float*)d_in[7];
    float* out = (float*)d_out;
    (void)in_sizes; (void)n_in; (void)out_size;

    optnet_qp_warp<<<1, 32>>>(L, p, G, z0, s0, out);
}

// round 3
// speedup vs baseline: 4.7543x; 1.9263x over previous
#include <cuda_runtime.h>
#include <math.h>

// OptNet_2525440770614 — warp-parallel 10-dim QP + log_softmax, FULL FP32.
//
// R2 post-mortem: fp64 on sm_103a is the bottleneck (DFMA lat ~47-64,
// rsqrt/div = long software DFMA chains). Reference solves in fp32 itself
// (its own rounding error vs exact is 5e-6), so fp32 here keeps us ~1e-5
// from the reference — 100x inside the 1e-3 tolerance.
//
// fp32: FFMA lat 4, rsqrtf = 1 MUFU (16cyc), fp32 div ~20cyc.
// Predicted kernel ~5k cycles.

#define NC 10
#define QP_EPS 1e-4f
#define FULL 0xffffffffu

__global__ void __launch_bounds__(32, 1)
optnet_qp_warp_f32(const float* __restrict__ L,
                   const float* __restrict__ p,
                   const float* __restrict__ G,
                   const float* __restrict__ z0,
                   const float* __restrict__ s0,
                   float* __restrict__ out) {
    __shared__ float sL[NC * NC];
    __shared__ float sQ[NC][NC];      // Q -> overwritten in place by Cholesky C
    __shared__ float rdiag[NC];       // 1/C[j][j] = rsqrt(updated diag)
    __shared__ float sg[NC];
    __shared__ float s_zu[NC], s_qg[NC];

    const int lane = threadIdx.x;

    // ---- stage L into shared (coalesced, 4 per lane max) ----
    #pragma unroll
    for (int t = 0; t < 4; t++) {
        int idx = lane + 32 * t;
        if (idx < NC * NC) sL[idx] = L[idx];
    }
    if (lane < NC) sg[lane] = G[lane];
    __syncwarp();

    // ---- build Q = tril(L) tril(L)^T + eps I (100 entries / 32 lanes) ----
    #pragma unroll
    for (int t = 0; t < 4; t++) {
        int idx = lane + 32 * t;
        if (idx < NC * NC) {
            int i = idx / NC, j = idx % NC;
            int m = (i < j) ? i : j;
            float s = 0.0f;
            #pragma unroll 10
            for (int k = 0; k <= m; k++)
                s = fmaf(sL[i * NC + k], sL[j * NC + k], s);
            if (i == j) s += QP_EPS;
            sQ[i][j] = s;
        }
    }

    // ---- h = s0 + g.z0 (independent chain, overlaps with Q build) ----
    float hacc = (lane < NC) ? G[lane] * z0[lane] : 0.0f;
    #pragma unroll
    for (int o = 16; o >= 1; o >>= 1) hacc += __shfl_xor_sync(FULL, hacc, o);
    const float h = hacc + s0[0];

    // ---- per-lane trailing-update pair assignments (55 lower-tri pairs) ----
    int pi[2], pk[2];
    #pragma unroll
    for (int t = 0; t < 2; t++) {
        int idx = lane + 32 * t;
        pi[t] = -1; pk[t] = -1;
        if (idx < 55) {
            int i = 0;
            while ((i + 1) * (i + 2) / 2 <= idx) i++;
            pi[t] = i;
            pk[t] = idx - i * (i + 1) / 2;
        }
    }
    __syncwarp();

    // ---- warp Cholesky, right-looking, rsqrtf-based (no divides) ----
    #pragma unroll
    for (int j = 0; j < NC; j++) {
        if (lane == j) rdiag[j] = rsqrtf(sQ[j][j]);
        __syncwarp();
        float rs = rdiag[j];
        if (lane >= j && lane < NC) sQ[lane][j] *= rs;   // col scale (diag -> sqrt)
        __syncwarp();
        #pragma unroll
        for (int t = 0; t < 2; t++) {
            if (pk[t] > j)
                sQ[pi[t]][pk[t]] = fmaf(-sQ[pi[t]][j], sQ[pk[t]][j], sQ[pi[t]][pk[t]]);
        }
        __syncwarp();
    }

    // ---- two simultaneous solves: lanes 0-9 rhs=-p, lanes 16-25 rhs=g ----
    const int base = (lane < 16) ? 0 : 16;
    const int row0 = lane - base;
    const int row  = (row0 < NC) ? row0 : NC - 1;
    const bool act = (row0 < NC);

    float acc = act ? ((base == 0) ? -p[row] : sg[row]) : 0.0f;

    // forward: C y = b
    float yreg = 0.0f;
    #pragma unroll
    for (int j = 0; j < NC; j++) {
        float v = acc * rdiag[j];
        float yj = __shfl_sync(FULL, v, base + j);
        if (act && row0 == j) yreg = yj;
        if (act && row0 > j)  acc = fmaf(-sQ[row][j], yj, acc);
    }
    // backward: C^T x = y
    acc = yreg;
    float xreg = 0.0f;
    #pragma unroll
    for (int j = NC - 1; j >= 0; j--) {
        float v = acc * rdiag[j];
        float xj = __shfl_sync(FULL, v, base + j);
        if (act && row0 == j) xreg = xj;
        if (act && row0 < j)  acc = fmaf(-sQ[j][row], xj, acc);
    }

    if (act && base == 0)  s_zu[row0] = xreg;
    if (act && base == 16) s_qg[row0] = xreg;

    // ---- dual-half butterfly: low half -> g.zu, high half -> g.qg ----
    float dot = act ? sg[row0] * xreg : 0.0f;
    #pragma unroll
    for (int o = 8; o >= 1; o >>= 1) dot += __shfl_xor_sync(FULL, dot, o);
    float gzu = __shfl_sync(FULL, dot, 0);    // g . z_unc
    float gqg = __shfl_sync(FULL, dot, 16);   // g . Q^-1 g
    __syncwarp();

    float viol = gzu - h;
    float lam = fmaxf(viol, 0.0f) / gqg;

    // ---- z, fp32 log_softmax ----
    float zf = (lane < NC) ? fmaf(-lam, s_qg[lane], s_zu[lane]) : -INFINITY;

    float mx = zf;
    #pragma unroll
    for (int o = 16; o >= 1; o >>= 1)
        mx = fmaxf(mx, __shfl_xor_sync(FULL, mx, o));
    float e = (lane < NC) ? expf(zf - mx) : 0.0f;
    float se = e;
    #pragma unroll
    for (int o = 16; o >= 1; o >>= 1) se += __shfl_xor_sync(FULL, se, o);
    float lse = logf(se);

    if (lane < NC) out[lane] = zf - mx - lse;
}

extern "C" void kernel_launch(void* const* d_in, const int* in_sizes, int n_in,
                              void* d_out, int out_size) {
    // metadata order: x, W1, b1, L, p, G, z0, s0
    const float* L  = (const float*)d_in[3];
    const float* p  = (const float*)d_in[4];
    const float* G  = (const float*)d_in[5];
    const float* z0 = (const float*)d_in[6];
    const float* s0 = (const float*)d_in[7];
    float* out = (float*)d_out;
    (void)in_sizes; (void)n_in; (void)out_size;

    optnet_qp_warp_f32<<<1, 32>>>(L, p, G, z0, s0, out);
}

// round 4
// speedup vs baseline: 9.3029x; 1.9567x over previous
#include <cuda_runtime.h>
#include <math.h>

// OptNet_2525440770614 — register-only warp QP solve, shuffle communication.
//
// R3 post-mortem: 12us kernel was dominated by shared-memory round trips
// (LDS 29) + __syncwarp (~23) + shfl (26) serial hops. This version holds
// everything in registers:
//   lane i owns row i of L/Q/C; Cholesky column broadcasts via shfl; during
//   step j, lane j captures the broadcast column as ct[] (=C[:,j]) so backward
//   substitution needs no transpose. Both RHS solved as two interleaved
//   accumulator chains (latency hiding). Zero smem, zero syncwarp.

#define NC 10
#define QP_EPS 1e-4f
#define FULL 0xffffffffu

__global__ void __launch_bounds__(32, 1)
optnet_qp_reg(const float* __restrict__ L,
              const float* __restrict__ p,
              const float* __restrict__ G,
              const float* __restrict__ z0,
              const float* __restrict__ s0,
              float* __restrict__ out) {
    const int lane = threadIdx.x;
    const bool act = (lane < NC);

    // ---- issue all global loads up front (independent, MLP-overlapped) ----
    float l[NC];                       // my row of L, tril-masked
    #pragma unroll
    for (int k = 0; k < NC; k++)
        l[k] = (act && k <= lane) ? L[lane * NC + k] : 0.0f;

    float gv   = act ? G[lane]  : 0.0f;
    float z0v  = act ? z0[lane] : 0.0f;
    float pv   = act ? p[lane]  : 0.0f;
    float s0v  = s0[0];

    // ---- h = s0 + g.z0 (butterfly) ----
    float hacc = gv * z0v;
    #pragma unroll
    for (int o = 16; o >= 1; o >>= 1) hacc += __shfl_xor_sync(FULL, hacc, o);
    const float h = hacc + s0v;

    // ---- Q row i in registers: q[j] = sum_k tril(L)[i][k]*tril(L)[j][k] ----
    float q[NC];
    #pragma unroll
    for (int j = 0; j < NC; j++) {
        float s = (j == lane) ? QP_EPS : 0.0f;
        #pragma unroll
        for (int k = 0; k <= j; k++)
            s = fmaf(l[k], __shfl_sync(FULL, l[k], j), s);
        q[j] = s;
    }

    // ---- register Cholesky (lane i = row i), rsqrt-based, no divides ----
    float rdiag[NC];
    float ct[NC];                      // ct[k] = C[k][lane]  (my column)
    #pragma unroll
    for (int k = 0; k < NC; k++) ct[k] = 0.0f;

    #pragma unroll
    for (int j = 0; j < NC; j++) {
        float d  = __shfl_sync(FULL, q[j], j);      // updated diag Q[j][j]
        float rs = rsqrtf(d);
        rdiag[j] = rs;                              // every lane keeps all 10
        float cj = q[j] * rs;                       // C[i][j] (valid i>=j)
        q[j] = cj;
        #pragma unroll
        for (int k = j + 1; k < NC; k++) {
            float ckj = __shfl_sync(FULL, cj, k);   // C[k][j]
            if (lane == j) ct[k] = ckj;             // capture my column
            q[k] = fmaf(-cj, ckj, q[k]);            // trailing update
        }
    }

    // ---- two RHS solved as interleaved chains: b1=-p, b2=g ----
    float a1 = -pv, a2 = gv;
    float y1 = 0.0f, y2 = 0.0f;

    // forward: C y = b
    #pragma unroll
    for (int j = 0; j < NC; j++) {
        float v1 = a1 * rdiag[j];
        float v2 = a2 * rdiag[j];
        float yj1 = __shfl_sync(FULL, v1, j);
        float yj2 = __shfl_sync(FULL, v2, j);
        if (lane == j) { y1 = yj1; y2 = yj2; }
        if (lane > j)  {
            a1 = fmaf(-q[j], yj1, a1);
            a2 = fmaf(-q[j], yj2, a2);
        }
    }
    // backward: C^T x = y   (uses my column ct[])
    a1 = y1; a2 = y2;
    float zu = 0.0f, qg = 0.0f;
    #pragma unroll
    for (int j = NC - 1; j >= 0; j--) {
        float v1 = a1 * rdiag[j];
        float v2 = a2 * rdiag[j];
        float xj1 = __shfl_sync(FULL, v1, j);
        float xj2 = __shfl_sync(FULL, v2, j);
        if (lane == j) { zu = xj1; qg = xj2; }
        if (lane < j) {
            a1 = fmaf(-ct[j], xj1, a1);
            a2 = fmaf(-ct[j], xj2, a2);
        }
    }

    // ---- viol = g.zu - h ; denom = g.qg  (two overlapped butterflies) ----
    float da = gv * zu;
    float db = gv * qg;
    #pragma unroll
    for (int o = 16; o >= 1; o >>= 1) {
        da += __shfl_xor_sync(FULL, da, o);
        db += __shfl_xor_sync(FULL, db, o);
    }
    float lam = __fdividef(fmaxf(da - h, 0.0f), db);

    // ---- z, log_softmax (MUFU fast paths) ----
    float zf = act ? fmaf(-lam, qg, zu) : -INFINITY;

    float mx = zf;
    #pragma unroll
    for (int o = 16; o >= 1; o >>= 1)
        mx = fmaxf(mx, __shfl_xor_sync(FULL, mx, o));
    float e = act ? __expf(zf - mx) : 0.0f;
    float se = e;
    #pragma unroll
    for (int o = 16; o >= 1; o >>= 1) se += __shfl_xor_sync(FULL, se, o);
    float lse = __logf(se);

    if (act) out[lane] = zf - mx - lse;
}

extern "C" void kernel_launch(void* const* d_in, const int* in_sizes, int n_in,
                              void* d_out, int out_size) {
    // metadata order: x, W1, b1, L, p, G, z0, s0
    const float* L  = (const float*)d_in[3];
    const float* p  = (const float*)d_in[4];
    const float* G  = (const float*)d_in[5];
    const float* z0 = (const float*)d_in[6];
    const float* s0 = (const float*)d_in[7];
    float* out = (float*)d_out;
    (void)in_sizes; (void)n_in; (void)out_size;

    optnet_qp_reg<<<1, 32>>>(L, p, G, z0, s0, out);
}

// round 5
// speedup vs baseline: 9.5320x; 1.0246x over previous
#include <cuda_runtime.h>
#include <math.h>

// OptNet_2525440770614 — register warp QP, Gauss-Jordan on [Q | -p, g].
//
// R4 post-mortem: Cholesky(10x~76cyc) + fwd/bwd(20x~34cyc) serial chain
// ~1450 cyc was the dominant path. Gauss-Jordan without pivoting (stable:
// Q is SPD, pivots = Schur diagonals > eps) solves BOTH rhs in one 10-step
// pass, ~54 cyc/step chain: the row-j element shuffles read lane j's
// unchanged row and overlap with the rcp+broadcast. Reductions cut to
// 4 butterfly steps (data confined to lanes 0-15).

#define NC 10
#define QP_EPS 1e-4f
#define FULL 0xffffffffu

__global__ void __launch_bounds__(32, 1)
optnet_qp_gj(const float* __restrict__ L,
             const float* __restrict__ p,
             const float* __restrict__ G,
             const float* __restrict__ z0,
             const float* __restrict__ s0,
             float* __restrict__ out) {
    const int lane = threadIdx.x;
    const bool act = (lane < NC);

    // ---- front-batched independent loads ----
    float l[NC];                        // my tril row of L
    #pragma unroll
    for (int k = 0; k < NC; k++)
        l[k] = (act && k <= lane) ? L[lane * NC + k] : 0.0f;

    float gv  = act ? G[lane]  : 0.0f;
    float z0v = act ? z0[lane] : 0.0f;
    float pv  = act ? p[lane]  : 0.0f;
    float s0v = s0[0];

    // ---- h = s0 + g.z0 (4-step butterfly: data in lanes 0-9 only) ----
    float hacc = gv * z0v;
    #pragma unroll
    for (int o = 8; o >= 1; o >>= 1) hacc += __shfl_xor_sync(FULL, hacc, o);
    const float h = __shfl_sync(FULL, hacc, 0) + s0v;   // uniform across warp

    // ---- Q row i: q[j] = sum_{k<=j} l_i[k] * l_j[k]  (+eps on diag) ----
    // all 55 shuffles independent (source l[] is static) -> pipelined
    float q[NC];
    #pragma unroll
    for (int j = 0; j < NC; j++) {
        float s = (j == lane) ? QP_EPS : 0.0f;
        #pragma unroll
        for (int k = 0; k <= j; k++)
            s = fmaf(l[k], __shfl_sync(FULL, l[k], j), s);
        q[j] = s;
    }

    // ---- Gauss-Jordan on [Q | r1=-p, r2=g], no pivoting (SPD) ----
    float r1 = -pv, r2 = gv;
    float myrcp = 1.0f;                 // 1/diag captured at my pivot step

    #pragma unroll
    for (int j = 0; j < NC; j++) {
        float rs_local = __fdividef(1.0f, q[j]);   // MUFU rcp path
        if (lane == j) myrcp = rs_local;           // static index capture
        float rs = __shfl_sync(FULL, rs_local, j); // pivot reciprocal
        float m  = q[j] * rs;                      // multiplier (lane j: 1)
        bool upd = (lane != j);
        // row-j elements: shuffles from lane j's UNchanged row, overlap rcp
        #pragma unroll
        for (int k = j + 1; k < NC; k++) {
            float qjk = __shfl_sync(FULL, q[k], j);
            if (upd) q[k] = fmaf(-m, qjk, q[k]);
        }
        float rj1 = __shfl_sync(FULL, r1, j);
        float rj2 = __shfl_sync(FULL, r2, j);
        if (upd) {
            r1 = fmaf(-m, rj1, r1);
            r2 = fmaf(-m, rj2, r2);
        }
    }

    // ---- solutions ----
    float zu = r1 * myrcp;              // Q^-1 (-p)
    float qg = r2 * myrcp;              // Q^-1 g
    if (!act) { zu = 0.0f; qg = 0.0f; }

    // ---- viol & denom: two overlapped 4-step butterflies ----
    float da = gv * zu;
    float db = gv * qg;
    #pragma unroll
    for (int o = 8; o >= 1; o >>= 1) {
        da += __shfl_xor_sync(FULL, da, o);
        db += __shfl_xor_sync(FULL, db, o);
    }
    float viol  = __shfl_sync(FULL, da, 0) - h;
    float denom = __shfl_sync(FULL, db, 0);
    float lam = __fdividef(fmaxf(viol, 0.0f), denom);

    // ---- z, log_softmax (fast MUFU) ----
    float zf = act ? fmaf(-lam, qg, zu) : -INFINITY;

    float mx = zf;
    #pragma unroll
    for (int o = 8; o >= 1; o >>= 1)
        mx = fmaxf(mx, __shfl_xor_sync(FULL, mx, o));
    mx = __shfl_sync(FULL, mx, 0);

    float e = act ? __expf(zf - mx) : 0.0f;
    float se = e;
    #pragma unroll
    for (int o = 8; o >= 1; o >>= 1) se += __shfl_xor_sync(FULL, se, o);
    float lse = __logf(__shfl_sync(FULL, se, 0));

    if (act) out[lane] = zf - mx - lse;
}

extern "C" void kernel_launch(void* const* d_in, const int* in_sizes, int n_in,
                              void* d_out, int out_size) {
    // metadata order: x, W1, b1, L, p, G, z0, s0
    const float* L  = (const float*)d_in[3];
    const float* p  = (const float*)d_in[4];
    const float* G  = (const float*)d_in[5];
    const float* z0 = (const float*)d_in[6];
    const float* s0 = (const float*)d_in[7];
    float* out = (float*)d_out;
    (void)in_sizes; (void)n_in; (void)out_size;

    optnet_qp_gj<<<1, 32>>>(L, p, G, z0, s0, out);
}